// round 2
// baseline (speedup 1.0000x reference)
#include <cuda_runtime.h>
#include <cstdint>

#define BATCH   64
#define NV      68
#define MC      46
#define ZL      384
#define NE      368
#define NITERS  5
#define MAXDEG  32
#define LLRCLIP 20.0f

// ---------------- device scratch (no cudaMalloc allowed) ----------------
__device__ int8_t g_c2v[BATCH * NE * ZL];      // c2v messages, VN-domain, value = 2*llr, int8
__device__ float  g_tot[BATCH * NV * ZL];      // total belief, [B][N][Z] layout (CN-gather friendly)
__device__ int    g_cn_edges[MC * MAXDEG];     // edges of each check
__device__ int    g_cn_deg[MC];

// ---------------- build check -> edge lists (tiny, deterministic) -------
__global__ void setup_kernel(const int* __restrict__ edge_cn) {
    int m = threadIdx.x;
    if (m < MC) {
        int d = 0;
        for (int e = 0; e < NE; e++) {
            if (edge_cn[e] == m && d < MAXDEG) g_cn_edges[m * MAXDEG + d++] = e;
        }
        g_cn_deg[m] = d;
    }
}

// ---------------- CN update (min-sum + quantize) -------------------------
// grid: (MC, BATCH), block: ZL threads (thread = z_c, CN-domain lifting index)
// reads tot (xa on first iter), old c2v; writes new c2v in place.
__global__ __launch_bounds__(ZL) void cn_kernel(
    const float* __restrict__ xa,
    const int*   __restrict__ edge_vn,
    const int*   __restrict__ edge_shift,
    const float* __restrict__ cn_weight,
    int it, int first)
{
    const int m  = blockIdx.x;
    const int b  = blockIdx.y;
    const int zc = threadIdx.x;

    __shared__ int s_e[MAXDEG], s_vn[MAXDEG], s_sh[MAXDEG];
    int deg = g_cn_deg[m];                 // uniform broadcast
    if (deg > MAXDEG) deg = MAXDEG;
    if ((int)threadIdx.x < deg) {
        int e = g_cn_edges[m * MAXDEG + threadIdx.x];
        s_e[threadIdx.x]  = e;
        s_vn[threadIdx.x] = edge_vn[e];
        s_sh[threadIdx.x] = edge_shift[e];
    }
    __syncthreads();

    const float w = cn_weight[it];
    const float* __restrict__ tot = first ? xa : g_tot;
    const int bN = b * NV;
    const int bE = b * NE;

    if (deg == 8) {
        // fast path: hold messages in registers, single gather pass
        float v[8]; int zz[8]; int ee[8];
        float m1 = 1e9f, m2 = 1e9f;
        int sgn = 0;
        #pragma unroll
        for (int k = 0; k < 8; k++) {
            int e = s_e[k];
            int z = zc - s_sh[k]; if (z < 0) z += ZL;
            float t = __ldg(&tot[(bN + s_vn[k]) * ZL + z]);
            float c = first ? 0.0f : 0.5f * (float)g_c2v[(bE + e) * ZL + z];
            float vv = fminf(fmaxf(t - c, -LLRCLIP), LLRCLIP);
            v[k] = vv; zz[k] = z; ee[k] = e;
            if (vv < 0.0f) sgn ^= 1;
            float mag = fabsf(vv);
            if (mag < m1)      { m2 = m1; m1 = mag; }
            else if (mag > m1) { m2 = fminf(m2, mag); }
        }
        #pragma unroll
        for (int k = 0; k < 8; k++) {
            float mag  = fabsf(v[k]);
            float emin = (mag == m1) ? m2 : m1;
            int neg    = (v[k] < 0.0f) ? 1 : 0;
            float sg   = (neg ^ sgn) ? -1.0f : 1.0f;
            float x    = w * sg * emin;
            // q = clip(rint(2x)/2, +-7.5)  -> store 2q as int8
            float q2   = fminf(fmaxf(rintf(2.0f * x), -15.0f), 15.0f);
            g_c2v[(bE + ee[k]) * ZL + zz[k]] = (int8_t)q2;
        }
    } else {
        // generic two-pass path (re-gathers hit L1)
        float m1 = 1e9f, m2 = 1e9f;
        int sgn = 0;
        for (int k = 0; k < deg; k++) {
            int z = zc - s_sh[k]; if (z < 0) z += ZL;
            float t = tot[(bN + s_vn[k]) * ZL + z];
            float c = first ? 0.0f : 0.5f * (float)g_c2v[(bE + s_e[k]) * ZL + z];
            float vv = fminf(fmaxf(t - c, -LLRCLIP), LLRCLIP);
            if (vv < 0.0f) sgn ^= 1;
            float mag = fabsf(vv);
            if (mag < m1)      { m2 = m1; m1 = mag; }
            else if (mag > m1) { m2 = fminf(m2, mag); }
        }
        for (int k = 0; k < deg; k++) {
            int z = zc - s_sh[k]; if (z < 0) z += ZL;
            float t = tot[(bN + s_vn[k]) * ZL + z];
            float c = first ? 0.0f : 0.5f * (float)g_c2v[(bE + s_e[k]) * ZL + z];
            float vv = fminf(fmaxf(t - c, -LLRCLIP), LLRCLIP);
            float mag  = fabsf(vv);
            float emin = (mag == m1) ? m2 : m1;
            int neg    = (vv < 0.0f) ? 1 : 0;
            float sg   = (neg ^ sgn) ? -1.0f : 1.0f;
            float x    = w * sg * emin;
            float q2   = fminf(fmaxf(rintf(2.0f * x), -15.0f), 15.0f);
            g_c2v[(bE + s_e[k]) * ZL + z] = (int8_t)q2;
        }
    }
}

// ---------------- VN update: tot = ch + sum(c2v), write tot + out --------
// grid: (ZL/128, BATCH), block: 128 threads (thread = z within chunk)
#define VCHUNK 128
#define SPAD   129
__global__ __launch_bounds__(VCHUNK) void vn_kernel(
    const float* __restrict__ xa,
    const int*   __restrict__ edge_vn,
    float*       __restrict__ out,     // d_out slab for this iteration, [B][Z][N]
    int write_tot)
{
    const int b  = blockIdx.y;
    const int z0 = blockIdx.x * VCHUNK;
    const int t  = threadIdx.x;

    __shared__ float s_tot[NV][SPAD];
    __shared__ int   s_vn[NE];

    for (int i = t; i < NE; i += VCHUNK) s_vn[i] = edge_vn[i];
    #pragma unroll 4
    for (int n = 0; n < NV; n++) s_tot[n][t] = 0.0f;
    __syncthreads();

    const int8_t* __restrict__ c2vb = g_c2v + (size_t)b * NE * ZL + z0 + t;
    #pragma unroll 4
    for (int e = 0; e < NE; e++) {
        float v = 0.5f * (float)c2vb[(size_t)e * ZL];
        s_tot[s_vn[e]][t] += v;            // column t is thread-private: no race
    }

    // add channel LLRs; write tot scratch ([B][N][Z], coalesced)
    #pragma unroll 4
    for (int n = 0; n < NV; n++) {
        float val = s_tot[n][t] + xa[((size_t)b * NV + n) * ZL + z0 + t];
        s_tot[n][t] = val;
        if (write_tot) g_tot[((size_t)b * NV + n) * ZL + z0 + t] = val;
    }
    __syncthreads();

    // transpose out of SMEM into the output slab [B][Z][N]
    float* __restrict__ ob = out + ((size_t)b * ZL + z0) * NV;
    for (int i = t; i < VCHUNK * NV; i += VCHUNK) {
        int z = i / NV, n = i - z * NV;
        ob[(size_t)z * NV + n] = s_tot[n][z];
    }
}

// ---------------- launch -------------------------------------------------
extern "C" void kernel_launch(void* const* d_in, const int* in_sizes, int n_in,
                              void* d_out, int out_size)
{
    const float* xa   = (const float*)d_in[0];  // [B][N][Z]
    const float* cnw  = (const float*)d_in[1];  // [NITERS]
    const int*   evn  = (const int*)  d_in[2];  // [E]
    const int*   ecn  = (const int*)  d_in[3];  // [E]
    const int*   esh  = (const int*)  d_in[4];  // [E]
    float*       out  = (float*)d_out;          // [NITERS][B][Z][N]

    setup_kernel<<<1, 64>>>(ecn);

    const size_t slab = (size_t)BATCH * ZL * NV;
    dim3 cn_grid(MC, BATCH);
    dim3 vn_grid(ZL / VCHUNK, BATCH);

    for (int it = 0; it < NITERS; it++) {
        cn_kernel<<<cn_grid, ZL>>>(xa, evn, esh, cnw, it, it == 0 ? 1 : 0);
        vn_kernel<<<vn_grid, VCHUNK>>>(xa, evn, out + (size_t)it * slab,
                                       it == NITERS - 1 ? 0 : 1);
    }
}

// round 8
// speedup vs baseline: 1.1324x; 1.1324x over previous
#include <cuda_runtime.h>
#include <cstdint>

#define BATCH   64
#define NV      68
#define MC      46
#define ZL      384
#define NE      368
#define NITERS  5
#define MAXDEG  16
#define LLRCLIP 20.0f

// ---------------- device scratch (no cudaMalloc allowed) ----------------
__device__ int8_t g_c2v[BATCH * NE * ZL];   // messages, CN-domain, value = 2*llr
__device__ float  g_tot[BATCH * NV * ZL];   // total belief, [B][N][Z]
__device__ float  g_acc[BATCH * NV * ZL];   // c2v sums (atomic), [B][N][Z]; zero-init & re-zeroed
__device__ int2   g_meta[MC * MAXDEG];      // .x = (vn*ZL)<<9 | shift, .y = e*ZL
__device__ int    g_cn_deg[MC];

// ---------------- build check -> edge metadata --------------------------
__global__ void setup_kernel(const int* __restrict__ edge_cn,
                             const int* __restrict__ edge_vn,
                             const int* __restrict__ edge_shift) {
    int m = threadIdx.x;
    if (m < MC) {
        int d = 0;
        for (int e = 0; e < NE; e++) {
            if (edge_cn[e] == m && d < MAXDEG) {
                int2 md;
                md.x = ((edge_vn[e] * ZL) << 9) | (edge_shift[e] & 511);
                md.y = e * ZL;
                g_meta[m * MAXDEG + d] = md;
                d++;
            }
        }
        g_cn_deg[m] = d;
    }
}

// ---------------- CN update: min-sum + quantize + fused VN scatter ------
// grid (MC, BATCH), block ZL. Reads tot (xa on iter 0), writes c2v int8 and
// accumulates 0.5*q into g_acc via fire-and-forget global atomics (exact:
// all values are multiples of 0.5, order-independent in fp32).
__global__ __launch_bounds__(ZL) void cn_kernel(
    const float* __restrict__ xa,
    const float* __restrict__ cn_weight,
    int it, int first)
{
    const int m  = blockIdx.x;
    const int b  = blockIdx.y;
    const int zc = threadIdx.x;

    __shared__ int2 s_md[MAXDEG];
    int deg = g_cn_deg[m];
    if (deg > MAXDEG) deg = MAXDEG;
    if ((int)threadIdx.x < deg) s_md[threadIdx.x] = g_meta[m * MAXDEG + threadIdx.x];
    __syncthreads();

    const float w = cn_weight[it];
    const float* __restrict__ tot = (first ? xa : g_tot) + (size_t)b * NV * ZL;
    float*       __restrict__ acc = g_acc + (size_t)b * NV * ZL;
    int8_t*      __restrict__ c2vb = g_c2v + (size_t)b * NE * ZL;

    if (deg == 8) {
        float vv[8]; int accoff[8], cidx[8];
        float m1 = 1e9f, m2 = 1e9f;
        int sgn = 0;
        #pragma unroll
        for (int k = 0; k < 8; k++) {
            int2 e = s_md[k];
            int z = zc - (e.x & 511); z += (z >> 31) & ZL;
            accoff[k] = (e.x >> 9) + z;
            cidx[k]   = e.y + zc;
            float c = first ? 0.0f : 0.5f * (float)c2vb[cidx[k]];
            float t = __ldg(&tot[accoff[k]]);
            float v = fminf(fmaxf(t - c, -LLRCLIP), LLRCLIP);
            vv[k] = v;
            if (v < 0.0f) sgn ^= 1;
            float mag = fabsf(v);
            if (mag < m1)      { m2 = m1; m1 = mag; }
            else if (mag > m1) { m2 = fminf(m2, mag); }
        }
        #pragma unroll
        for (int k = 0; k < 8; k++) {
            float mag  = fabsf(vv[k]);
            float emin = (mag == m1) ? m2 : m1;
            bool flip  = (vv[k] < 0.0f) ^ (sgn != 0);
            float x    = (flip ? -w : w) * emin;
            float q2   = fminf(fmaxf(rintf(x + x), -15.0f), 15.0f);
            c2vb[cidx[k]] = (int8_t)q2;
            atomicAdd(&acc[accoff[k]], 0.5f * q2);
        }
    } else {
        // generic fallback (dataset uses deg==8)
        float m1 = 1e9f, m2 = 1e9f;
        int sgn = 0;
        for (int k = 0; k < deg; k++) {
            int2 e = s_md[k];
            int z = zc - (e.x & 511); z += (z >> 31) & ZL;
            float c = first ? 0.0f : 0.5f * (float)c2vb[e.y + zc];
            float v = fminf(fmaxf(tot[(e.x >> 9) + z] - c, -LLRCLIP), LLRCLIP);
            if (v < 0.0f) sgn ^= 1;
            float mag = fabsf(v);
            if (mag < m1)      { m2 = m1; m1 = mag; }
            else if (mag > m1) { m2 = fminf(m2, mag); }
        }
        for (int k = 0; k < deg; k++) {
            int2 e = s_md[k];
            int z = zc - (e.x & 511); z += (z >> 31) & ZL;
            int ao = (e.x >> 9) + z;
            float c = first ? 0.0f : 0.5f * (float)c2vb[e.y + zc];
            float v = fminf(fmaxf(tot[ao] - c, -LLRCLIP), LLRCLIP);
            float mag  = fabsf(v);
            float emin = (mag == m1) ? m2 : m1;
            bool flip  = (v < 0.0f) ^ (sgn != 0);
            float x    = (flip ? -w : w) * emin;
            float q2   = fminf(fmaxf(rintf(x + x), -15.0f), 15.0f);
            c2vb[e.y + zc] = (int8_t)q2;
            atomicAdd(&acc[ao], 0.5f * q2);
        }
    }
}

// ---------------- finalize: tot = xa + acc, acc = 0, out = tot^T --------
// grid (ZL/32, ceil(NV/32), BATCH), block (32, 8). 32x32 tile transpose.
__global__ __launch_bounds__(256) void finalize_kernel(
    const float* __restrict__ xa,
    float*       __restrict__ out,     // slab for this iter: [B][ZL][NV]
    int write_tot)
{
    __shared__ float tile[32][33];

    const int b  = blockIdx.z;
    const int z0 = blockIdx.x * 32;
    const int n0 = blockIdx.y * 32;
    const int tx = threadIdx.x;          // z within tile (load) / n (store)
    const int ty = threadIdx.y;

    const size_t base = (size_t)b * NV * ZL;
    const float* __restrict__ xab = xa + base;
    float* __restrict__ accb = g_acc + base;
    float* __restrict__ totb = g_tot + base;

    #pragma unroll
    for (int j = 0; j < 4; j++) {
        int nl = ty + j * 8;
        int n  = n0 + nl;
        if (n < NV) {
            int idx = n * ZL + z0 + tx;
            float val = xab[idx] + accb[idx];
            accb[idx] = 0.0f;
            if (write_tot) totb[idx] = val;
            tile[nl][tx] = val;
        }
    }
    __syncthreads();

    // out[b][z][n] = tile[n - n0][z - z0]; consecutive tx -> consecutive n
    float* __restrict__ ob = out + ((size_t)b * ZL + z0) * NV;
    int n = n0 + tx;
    if (n < NV) {
        #pragma unroll
        for (int j = 0; j < 4; j++) {
            int zl = ty + j * 8;
            ob[(size_t)zl * NV + n] = tile[tx][zl];
        }
    }
}

// ---------------- launch -------------------------------------------------
extern "C" void kernel_launch(void* const* d_in, const int* in_sizes, int n_in,
                              void* d_out, int out_size)
{
    const float* xa   = (const float*)d_in[0];  // [B][N][Z]
    const float* cnw  = (const float*)d_in[1];  // [NITERS]
    const int*   evn  = (const int*)  d_in[2];  // [E]
    const int*   ecn  = (const int*)  d_in[3];  // [E]
    const int*   esh  = (const int*)  d_in[4];  // [E]
    float*       out  = (float*)d_out;          // [NITERS][B][Z][N]

    setup_kernel<<<1, 64>>>(ecn, evn, esh);

    const size_t slab = (size_t)BATCH * ZL * NV;
    dim3 cn_grid(MC, BATCH);
    dim3 fin_grid(ZL / 32, (NV + 31) / 32, BATCH);
    dim3 fin_blk(32, 8);

    for (int it = 0; it < NITERS; it++) {
        cn_kernel<<<cn_grid, ZL>>>(xa, cnw, it, it == 0 ? 1 : 0);
        // finalize always zeroes g_acc (keeps graph replays deterministic);
        // skips the g_tot write after the last iteration.
        finalize_kernel<<<fin_grid, fin_blk>>>(xa, out + (size_t)it * slab,
                                               it == NITERS - 1 ? 0 : 1);
    }
}